// round 16
// baseline (speedup 1.0000x reference)
#include <cuda_runtime.h>
#include <cuda_bf16.h>
#include <cuda_fp16.h>
#include <cstdint>

// ----------------------------------------------------------------------------
// GCN: 5x (GCNConv + ReLU) + global mean pool + linear head.
//   Fixed shapes: N=100000, E=1600000, H=128, C=10, L=5, G=64
//   - norm = dis[s]*dis[d] factored: dis[s] in stored activations, dis[d]
//     applied per SpMM row; edges carry only src (4B).
//   - All activations fp16; SpMM fp32-accumulates; GEMM mma.m16n8k16.f16
//     with 2-term compensated W (hi + residual) -> W to 22 bits.
//   - PER-LAYER FUSED PRODUCER/CONSUMER KERNEL: groups of 9 blocks =
//     8 SpMM blocks (64 rows) + 1 GEMM block (that 64-row tile). bid-ordered
//     dispatch interleaves gather and tensor work across the whole layer;
//     GEMM blocks spin on a per-tile arrive counter (release/acquire).
//     Deadlock-free: consumers wait only on strictly-lower-bid producers.
// ----------------------------------------------------------------------------

#define MAXN 100352
#define MAXT 1703936      // >= E + N
#define MAXG 1024
#define MAXL 8
#define HH   128

__device__ int     g_cnt[MAXN];
__device__ float   g_dis[MAXN];
__device__ int     g_rowptr[MAXN + 1];
__device__ int     g_cursor[MAXN];
__device__ int     g_edges[MAXT];               // src only
__device__ __half  g_xh0[(size_t)MAXN * HH];    // dis-scaled fp16 input
__device__ __half  g_aggh[(size_t)MAXN * HH];   // fp16 aggregate
__device__ __half  g_xh1[(size_t)MAXN * HH];
__device__ __half  g_xh2[(size_t)MAXN * HH];
__device__ int     g_bsum[256];
__device__ int     g_gstart[MAXG + 1];
__device__ float   g_psum[(size_t)MAXG * HH];
__device__ uint2   g_wh[MAXL * 4096];   // W fp16-hi fragments (all layers)
__device__ uint2   g_wl[MAXL * 4096];   // W fp16-residual fragments
__device__ int     g_tilecnt[MAXL * 2048];  // per-layer 64-row tile arrive counters

// ------------------------------- graph prep ---------------------------------
__global__ void k_count(const int* __restrict__ dst, int* cnt, int e) {
    int i = blockIdx.x * blockDim.x + threadIdx.x;
    if (i < e) atomicAdd(&cnt[dst[i]], 1);
}

__global__ void k_scan1(const int* __restrict__ cnt, int* bsum, float* dis, int n) {
    __shared__ int sh[256];
    int t = threadIdx.x;
    int base = blockIdx.x * 1024 + t * 4;
    int s = 0;
#pragma unroll
    for (int i = 0; i < 4; i++)
        if (base + i < n) {
            int c = cnt[base + i];
            s += c;
            dis[base + i] = rsqrtf((float)c);   // cnt >= 1 always (self loop)
        }
    sh[t] = s;
    __syncthreads();
#pragma unroll
    for (int off = 128; off > 0; off >>= 1) {
        if (t < off) sh[t] += sh[t + off];
        __syncthreads();
    }
    if (t == 0) bsum[blockIdx.x] = sh[0];
}

__global__ void k_scan2(int* bsum, int* rowptr, int nb, int n) {
    __shared__ int sh[256];
    int t = threadIdx.x;
    sh[t] = (t < nb) ? bsum[t] : 0;
    __syncthreads();
    for (int off = 1; off < 256; off <<= 1) {
        int v = (t >= off) ? sh[t - off] : 0;
        __syncthreads();
        sh[t] += v;
        __syncthreads();
    }
    if (t < nb) bsum[t] = (t == 0) ? 0 : sh[t - 1];
    if (t == 0) rowptr[n] = sh[nb - 1];
}

__global__ void k_scan3(const int* __restrict__ cnt, const int* __restrict__ bsumex,
                        int* rowptr, int* cursor, int n) {
    __shared__ int sh[256];
    int t = threadIdx.x;
    int base = blockIdx.x * 1024 + t * 4;
    int v0 = 0, v1 = 0, v2 = 0, v3 = 0;
    if (base + 0 < n) v0 = cnt[base + 0];
    if (base + 1 < n) v1 = cnt[base + 1];
    if (base + 2 < n) v2 = cnt[base + 2];
    if (base + 3 < n) v3 = cnt[base + 3];
    int s = v0 + v1 + v2 + v3;
    sh[t] = s;
    __syncthreads();
    for (int off = 1; off < 256; off <<= 1) {
        int v = (t >= off) ? sh[t - off] : 0;
        __syncthreads();
        sh[t] += v;
        __syncthreads();
    }
    int ex = (t == 0) ? 0 : sh[t - 1];
    int off0 = bsumex[blockIdx.x] + ex;
    if (base + 0 < n) { rowptr[base + 0] = off0;                cursor[base + 0] = off0; }
    if (base + 1 < n) { rowptr[base + 1] = off0 + v0;           cursor[base + 1] = off0 + v0; }
    if (base + 2 < n) { rowptr[base + 2] = off0 + v0 + v1;      cursor[base + 2] = off0 + v0 + v1; }
    if (base + 3 < n) { rowptr[base + 3] = off0 + v0 + v1 + v2; cursor[base + 3] = off0 + v0 + v1 + v2; }
}

__global__ void k_fill(const int* __restrict__ src, const int* __restrict__ dst,
                       int* cursor, int* edges, int e, int n) {
    int i = blockIdx.x * blockDim.x + threadIdx.x;
    if (i >= e + n) return;
    int s, d;
    if (i < e) { s = src[i]; d = dst[i]; }
    else       { s = d = i - e; }
    int pos = atomicAdd(&cursor[d], 1);
    edges[pos] = s;
}

// ---------------- input fp32 -> dis-scaled fp16 convert ----------------------
__global__ void k_cvt(const float* __restrict__ x, const float* __restrict__ dis,
                      __half* __restrict__ xh, int n) {
    int i = blockIdx.x * blockDim.x + threadIdx.x;   // one per 4 elements
    if (i >= n * 32) return;
    float sc = dis[i >> 5];
    float4 v = ((const float4*)x)[i];
    __half2 a = __floats2half2_rn(v.x * sc, v.y * sc);
    __half2 b = __floats2half2_rn(v.z * sc, v.w * sc);
    ((uint2*)xh)[i] = make_uint2(*(uint32_t*)&a, *(uint32_t*)&b);
}

// ------------------------- tensor-core GEMM helpers --------------------------
__device__ __forceinline__ uint32_t pack_h2(__half lo, __half hi) {
    __half2 h = __halves2half2(lo, hi);
    return *reinterpret_cast<uint32_t*>(&h);
}
__device__ __forceinline__ void mma16816(float* c,
                                         uint32_t a0, uint32_t a1, uint32_t a2, uint32_t a3,
                                         uint32_t b0, uint32_t b1) {
    asm volatile(
        "mma.sync.aligned.m16n8k16.row.col.f32.f16.f16.f32 "
        "{%0,%1,%2,%3}, {%4,%5,%6,%7}, {%8,%9}, {%0,%1,%2,%3};"
        : "+f"(c[0]), "+f"(c[1]), "+f"(c[2]), "+f"(c[3])
        : "r"(a0), "r"(a1), "r"(a2), "r"(a3), "r"(b0), "r"(b1));
}

// ----------------- per-layer W fragment pre-split (ALL layers) ---------------
__global__ void k_prepw16(const float* __restrict__ Ws, uint2* __restrict__ wh,
                          uint2* __restrict__ wl) {
    int l = blockIdx.x >> 4;
    int idx = (blockIdx.x & 15) * 256 + threadIdx.x;   // 0..4095
    const float* W = Ws + (size_t)l * HH * HH;
    int lane = idx & 31, tile = idx >> 5;              // tile 0..127
    int nt = tile & 15, ks = tile >> 4;                // ks 0..7
    int nn = nt * 8 + (lane >> 2);
    int k0 = ks * 16 + (lane & 3) * 2;
    float v00 = W[k0 * HH + nn],       v01 = W[(k0 + 1) * HH + nn];
    float v10 = W[(k0 + 8) * HH + nn], v11 = W[(k0 + 9) * HH + nn];
    __half h00 = __float2half_rn(v00), h01 = __float2half_rn(v01);
    __half h10 = __float2half_rn(v10), h11 = __float2half_rn(v11);
    __half r00 = __float2half_rn(v00 - __half2float(h00));
    __half r01 = __float2half_rn(v01 - __half2float(h01));
    __half r10 = __float2half_rn(v10 - __half2float(h10));
    __half r11 = __float2half_rn(v11 - __half2float(h11));
    wh[l * 4096 + idx] = make_uint2(pack_h2(h00, h01), pack_h2(h10, h11));
    wl[l * 4096 + idx] = make_uint2(pack_h2(r00, r01), pack_h2(r10, r11));
}

// ----------------------- fused per-layer producer/consumer -------------------
// Groups of 9 blocks: r=0..7 -> SpMM block (8 rows, warp-per-row), r=8 -> GEMM
// block for the 64-row tile those 8 produced. GEMM spins on tilecnt[tile].
#define SMEM_L (64 * 136 * 2)

__global__ __launch_bounds__(256, 3)
void k_layer(const int* __restrict__ rowptr, const int* __restrict__ edges,
             const float* __restrict__ dis, const __half* __restrict__ xin,
             __half* __restrict__ aggh,
             const uint2* __restrict__ wh, const uint2* __restrict__ wl,
             const float* __restrict__ bias, __half* __restrict__ xout,
             int* __restrict__ tilecnt, int last, int nspmm, int n) {
    const int tid = threadIdx.x;
    const int grp = blockIdx.x / 9;
    const int r   = blockIdx.x % 9;

    if (r < 8) {
        // ======================= SpMM role =======================
        int sb = grp * 8 + r;                // spmm block index
        if (sb >= nspmm) return;
        int row  = sb * 8 + (tid >> 5);
        int lane = tid & 31;
        if (row < n) {
            int s = rowptr[row], e = rowptr[row + 1];
            const uint2* xp = (const uint2*)xin;
            float4 acc = make_float4(0.f, 0.f, 0.f, 0.f);
            int j = s;
            for (; j + 4 <= e; j += 4) {
                int s0 = __ldg(&edges[j + 0]);
                int s1 = __ldg(&edges[j + 1]);
                int s2 = __ldg(&edges[j + 2]);
                int s3 = __ldg(&edges[j + 3]);
                uint2 h0 = __ldg(&xp[(size_t)s0 * 32 + lane]);
                uint2 h1 = __ldg(&xp[(size_t)s1 * 32 + lane]);
                uint2 h2 = __ldg(&xp[(size_t)s2 * 32 + lane]);
                uint2 h3 = __ldg(&xp[(size_t)s3 * 32 + lane]);
                float2 a, b;
                a = __half22float2(*(const __half2*)&h0.x); b = __half22float2(*(const __half2*)&h0.y);
                acc.x += a.x; acc.y += a.y; acc.z += b.x; acc.w += b.y;
                a = __half22float2(*(const __half2*)&h1.x); b = __half22float2(*(const __half2*)&h1.y);
                acc.x += a.x; acc.y += a.y; acc.z += b.x; acc.w += b.y;
                a = __half22float2(*(const __half2*)&h2.x); b = __half22float2(*(const __half2*)&h2.y);
                acc.x += a.x; acc.y += a.y; acc.z += b.x; acc.w += b.y;
                a = __half22float2(*(const __half2*)&h3.x); b = __half22float2(*(const __half2*)&h3.y);
                acc.x += a.x; acc.y += a.y; acc.z += b.x; acc.w += b.y;
            }
            for (; j < e; j++) {
                int s0 = __ldg(&edges[j]);
                uint2 h = __ldg(&xp[(size_t)s0 * 32 + lane]);
                float2 a = __half22float2(*(const __half2*)&h.x);
                float2 b = __half22float2(*(const __half2*)&h.y);
                acc.x += a.x; acc.y += a.y; acc.z += b.x; acc.w += b.y;
            }
            float dd = __ldg(&dis[row]);
            __half2 o0 = __floats2half2_rn(acc.x * dd, acc.y * dd);
            __half2 o1 = __floats2half2_rn(acc.z * dd, acc.w * dd);
            ((uint2*)aggh)[(size_t)row * 32 + lane] = make_uint2(*(uint32_t*)&o0, *(uint32_t*)&o1);
        }
        __threadfence();
        __syncthreads();
        if (tid == 0) atomicAdd(&tilecnt[sb >> 3], 1);
        return;
    }

    // ======================= GEMM role (64-row tile grp) =======================
    const int m0 = grp << 6;
    if (m0 >= n) return;
    extern __shared__ __half As[];                 // [64][136]

    if (tid == 0) {
        int target = min(8, nspmm - grp * 8);
        int v;
        do {
            asm volatile("ld.acquire.gpu.s32 %0, [%1];" : "=r"(v)
                         : "l"(tilecnt + grp) : "memory");
            if (v < target) __nanosleep(128);
        } while (v < target);
    }
    __syncthreads();

    // stage 64-row A tile (fp16, coalesced uint4, padded smem)
#pragma unroll
    for (int i = 0; i < 4; i++) {
        int s   = tid + i * 256;       // 0..1023
        int row = s >> 4, cb = s & 15;
        uint4 v = make_uint4(0u, 0u, 0u, 0u);
        if (m0 + row < n)
            v = ((const uint4*)(aggh + (size_t)(m0 + row) * HH))[cb];
        *(uint4*)&As[row * 136 + cb * 8] = v;
    }
    __syncthreads();

    const int lane = tid & 31;
    const int warp = tid >> 5;
    const int wm = warp >> 2;      // 0..1  (32 rows each)
    const int wn = warp & 3;       // 0..3  (32 cols each)
    const uint32_t as_base = (uint32_t)__cvta_generic_to_shared(As);

    float acc[2][4][4];
#pragma unroll
    for (int a = 0; a < 2; a++)
#pragma unroll
        for (int b = 0; b < 4; b++)
#pragma unroll
            for (int c = 0; c < 4; c++) acc[a][b][c] = 0.f;

    const int lrow = lane & 15;
    const int lcol = (lane >> 4) * 8;

#pragma unroll
    for (int ks = 0; ks < 8; ks++) {
        uint2 bh[4], bl[4];
#pragma unroll
        for (int nt = 0; nt < 4; nt++) {
            int slot = (ks * 16 + wn * 4 + nt) * 32 + lane;
            bh[nt] = __ldg(&wh[slot]);
            bl[nt] = __ldg(&wl[slot]);
        }
        uint32_t af[2][4];
#pragma unroll
        for (int mt = 0; mt < 2; mt++) {
            int row = wm * 32 + mt * 16 + lrow;
            int col = ks * 16 + lcol;
            uint32_t addr = as_base + (uint32_t)(row * 136 + col) * 2;
            asm volatile(
                "ldmatrix.sync.aligned.m8n8.x4.shared.b16 {%0,%1,%2,%3}, [%4];"
                : "=r"(af[mt][0]), "=r"(af[mt][1]), "=r"(af[mt][2]), "=r"(af[mt][3])
                : "r"(addr));
        }
#pragma unroll
        for (int mt = 0; mt < 2; mt++)
#pragma unroll
            for (int nt = 0; nt < 4; nt++) {
                mma16816(acc[mt][nt], af[mt][0], af[mt][1], af[mt][2], af[mt][3],
                         bh[nt].x, bh[nt].y);
                mma16816(acc[mt][nt], af[mt][0], af[mt][1], af[mt][2], af[mt][3],
                         bl[nt].x, bl[nt].y);
            }
    }

    // epilogue: bias + relu + (dis scale) + fp16 store
    const int g = lane >> 2, t = lane & 3;
#pragma unroll
    for (int nt = 0; nt < 4; nt++) {
        int c = wn * 32 + nt * 8 + 2 * t;
        float b0 = __ldg(&bias[c]), b1 = __ldg(&bias[c + 1]);
#pragma unroll
        for (int mt = 0; mt < 2; mt++) {
            int m = m0 + wm * 32 + mt * 16 + g;
            if (m < n) {
                float sc = last ? 1.0f : __ldg(&dis[m]);
                float o0 = fmaxf(acc[mt][nt][0] + b0, 0.f) * sc;
                float o1 = fmaxf(acc[mt][nt][1] + b1, 0.f) * sc;
                *(__half2*)&xout[(size_t)m * HH + c] = __floats2half2_rn(o0, o1);
            }
            if (m + 8 < n) {
                float sc = last ? 1.0f : __ldg(&dis[m + 8]);
                float o0 = fmaxf(acc[mt][nt][2] + b0, 0.f) * sc;
                float o1 = fmaxf(acc[mt][nt][3] + b1, 0.f) * sc;
                *(__half2*)&xout[(size_t)(m + 8) * HH + c] = __floats2half2_rn(o0, o1);
            }
        }
    }
}

// ------------------------------ pooling / head ------------------------------
__global__ void k_gbz(const int* __restrict__ batch, int* gstart, float* psum,
                      int* cnt, int* tilecnt, int n, int g_num) {
    int i = blockIdx.x * blockDim.x + threadIdx.x;
    if (i < n) cnt[i] = 1;                 // self loop seed for k_count
    if (i < g_num * HH) psum[i] = 0.f;
    if (i < MAXL * 2048) tilecnt[i] = 0;
    if (i <= g_num) {
        int lo = 0, hi = n;
        while (lo < hi) {
            int mid = (lo + hi) >> 1;
            if (batch[mid] < i) lo = mid + 1; else hi = mid;
        }
        gstart[i] = lo;
    }
}

__global__ __launch_bounds__(128)
void k_psum(const __half* __restrict__ x, const int* __restrict__ batch,
            float* __restrict__ psum, int n) {
    __shared__ int bsh[256];
    const int t = threadIdx.x;            // column 0..127
    const int r0 = blockIdx.x * 256;
    const int len = min(256, n - r0);
    for (int i = t; i < len; i += 128) bsh[i] = batch[r0 + i];
    __syncthreads();

    if (bsh[0] == bsh[len - 1]) {
        float acc = 0.f;
        int i = 0;
        for (; i + 8 <= len; i += 8) {
            float v0 = __half2float(x[(size_t)(r0 + i + 0) * HH + t]);
            float v1 = __half2float(x[(size_t)(r0 + i + 1) * HH + t]);
            float v2 = __half2float(x[(size_t)(r0 + i + 2) * HH + t]);
            float v3 = __half2float(x[(size_t)(r0 + i + 3) * HH + t]);
            float v4 = __half2float(x[(size_t)(r0 + i + 4) * HH + t]);
            float v5 = __half2float(x[(size_t)(r0 + i + 5) * HH + t]);
            float v6 = __half2float(x[(size_t)(r0 + i + 6) * HH + t]);
            float v7 = __half2float(x[(size_t)(r0 + i + 7) * HH + t]);
            acc += ((v0 + v1) + (v2 + v3)) + ((v4 + v5) + (v6 + v7));
        }
        for (; i < len; i++) acc += __half2float(x[(size_t)(r0 + i) * HH + t]);
        atomicAdd(&psum[(size_t)bsh[0] * HH + t], acc);
    } else {
        float acc = 0.f;
        int curg = bsh[0];
        for (int i = 0; i < len; i++) {
            int g = bsh[i];
            if (g != curg) { atomicAdd(&psum[(size_t)curg * HH + t], acc); acc = 0.f; curg = g; }
            acc += __half2float(x[(size_t)(r0 + i) * HH + t]);
        }
        atomicAdd(&psum[(size_t)curg * HH + t], acc);
    }
}

__global__ void k_out(const float* __restrict__ psum, const int* __restrict__ gstart,
                      const float* __restrict__ Wout, const float* __restrict__ bout,
                      float* __restrict__ out, int C) {
    __shared__ float pr[HH];
    int g = blockIdx.x, t = threadIdx.x;
    float cntf = (float)(gstart[g + 1] - gstart[g]);
    float inv = 1.0f / fmaxf(cntf, 1.0f);
    pr[t] = psum[(size_t)g * HH + t] * inv;
    __syncthreads();
    if (t < C) {
        float s = bout[t];
#pragma unroll 8
        for (int k = 0; k < HH; k++) s += pr[k] * Wout[k * C + t];
        out[g * C + t] = s;
    }
}

// --------------------------------- launch -----------------------------------
extern "C" void kernel_launch(void* const* d_in, const int* in_sizes, int n_in,
                              void* d_out, int out_size) {
    const float* x     = (const float*)d_in[0];
    const int*   ei    = (const int*)d_in[1];
    const int*   batch = (const int*)d_in[2];
    int iw, ibs, iwo, ibo;
    if (n_in >= 8) { iw = 4; ibs = 5; iwo = 6; ibo = 7; }  // num_graphs at index 3
    else           { iw = 3; ibs = 4; iwo = 5; ibo = 6; }
    const float* Ws   = (const float*)d_in[iw];
    const float* bs   = (const float*)d_in[ibs];
    const float* Wout = (const float*)d_in[iwo];
    const float* bout = (const float*)d_in[ibo];

    int N = in_sizes[2];
    int E = in_sizes[1] / 2;
    int H = in_sizes[0] / N;            // expect 128
    int C = in_sizes[ibo];
    int L = in_sizes[ibs] / H;
    int G = out_size / C;
    if (N > MAXN || (E + N) > MAXT || G > MAXG || H != HH || L > MAXL) return;

    void* p;
    cudaGetSymbolAddress(&p, g_cnt);     int*     cnt     = (int*)p;
    cudaGetSymbolAddress(&p, g_dis);     float*   dis     = (float*)p;
    cudaGetSymbolAddress(&p, g_rowptr);  int*     rowptr  = (int*)p;
    cudaGetSymbolAddress(&p, g_cursor);  int*     cursor  = (int*)p;
    cudaGetSymbolAddress(&p, g_edges);   int*     edges   = (int*)p;
    cudaGetSymbolAddress(&p, g_xh0);     __half*  xh0     = (__half*)p;
    cudaGetSymbolAddress(&p, g_aggh);    __half*  aggh    = (__half*)p;
    cudaGetSymbolAddress(&p, g_xh1);     __half*  xh1     = (__half*)p;
    cudaGetSymbolAddress(&p, g_xh2);     __half*  xh2     = (__half*)p;
    cudaGetSymbolAddress(&p, g_bsum);    int*     bsum    = (int*)p;
    cudaGetSymbolAddress(&p, g_gstart);  int*     gstart  = (int*)p;
    cudaGetSymbolAddress(&p, g_psum);    float*   psum    = (float*)p;
    cudaGetSymbolAddress(&p, g_wh);      uint2*   wh      = (uint2*)p;
    cudaGetSymbolAddress(&p, g_wl);      uint2*   wl      = (uint2*)p;
    cudaGetSymbolAddress(&p, g_tilecnt); int*     tilecnt = (int*)p;

    cudaFuncSetAttribute(k_layer, cudaFuncAttributeMaxDynamicSharedMemorySize, SMEM_L);

    const int* src = ei;
    const int* dst = ei + E;

    // init cnt=1 / graph boundaries / zero psum + tilecnt (one pass)
    k_gbz<<<(N + 255) / 256, 256>>>(batch, gstart, psum, cnt, tilecnt, N, G);
    // W fragment pre-split for all layers (off the per-layer critical path)
    k_prepw16<<<16 * L, 256>>>(Ws, wh, wl);

    k_count<<<(E + 255) / 256, 256>>>(dst, cnt, E);

    int NB = (N + 1023) / 1024;
    k_scan1<<<NB, 256>>>(cnt, bsum, dis, N);
    // dis-scaled fp16 input (needs dis -> after scan1)
    k_cvt<<<(N * 32 + 255) / 256, 256>>>(x, dis, xh0, N);
    k_scan2<<<1, 256>>>(bsum, rowptr, NB, N);
    k_scan3<<<NB, 256>>>(cnt, bsum, rowptr, cursor, N);
    k_fill <<<(E + N + 255) / 256, 256>>>(src, dst, cursor, edges, E, N);

    int nspmm = (N + 7) / 8;
    int ngrp  = (nspmm + 7) / 8;     // 64-row tiles
    int gridL = ngrp * 9;

    const __half* xin = xh0;
    for (int l = 0; l < L; l++) {
        int last = (l == L - 1);
        __half* xout = (l & 1) ? xh2 : xh1;
        k_layer<<<gridL, 256, SMEM_L>>>(rowptr, edges, dis, xin, aggh,
                                        wh + (size_t)l * 4096, wl + (size_t)l * 4096,
                                        bs + (size_t)l * H, xout,
                                        tilecnt + l * 2048, last, nspmm, N);
        xin = xout;
    }

    k_psum<<<(N + 255) / 256, 128>>>(xin, batch, psum, N);
    k_out <<<G, HH>>>(psum, gstart, Wout, bout, (float*)d_out, C);
}

// round 17
// speedup vs baseline: 2.1179x; 2.1179x over previous
#include <cuda_runtime.h>
#include <cuda_bf16.h>
#include <cuda_fp16.h>
#include <cstdint>

// ----------------------------------------------------------------------------
// GCN: 5x (GCNConv + ReLU) + global mean pool + linear head.
//   Fixed shapes: N=100000, E=1600000, H=128, C=10, L=5, G=64
//   - Ordinal CSR build: k_count's atomicAdd return value IS the edge's slot
//     within its row -> k_fill needs no cursor and no atomics.
//   - All activations fp16 (noise pools away; fp8 measured too coarse).
//   - SpMM: warp-per-row fp16 gather (unroll 8), fp32 accumulate, fp16 out.
//     SEPARATE kernel from GEMM (fusion measured catastrophic twice: gather
//     needs ~48 thin warps/SM, incompatible with tensor-role reg/smem).
//   - GEMM: mma.m16n8k16.f16, fp32 accumulate, 2 terms:
//       A(fp16, exact) x [W_hi(fp16) + W_lo(fp16 residual)] -> W to 22 bits.
//   - Chunked mean-pool (sorted batch) reads fp16.
// ----------------------------------------------------------------------------

#define MAXN 100352
#define MAXT 1703936      // >= E + N
#define MAXG 1024
#define MAXL 8
#define HH   128

__device__ int     g_cnt[MAXN];
__device__ float   g_dis[MAXN];
__device__ int     g_rowptr[MAXN + 1];
__device__ int     g_ord[MAXT];                 // per-edge within-row ordinal
__device__ int2    g_edges[MAXT];               // {src, w}
__device__ __half  g_xh0[(size_t)MAXN * HH];    // converted fp16 input
__device__ __half  g_aggh[(size_t)MAXN * HH];   // fp16 aggregate
__device__ __half  g_xh1[(size_t)MAXN * HH];
__device__ __half  g_xh2[(size_t)MAXN * HH];
__device__ int     g_bsum[256];
__device__ int     g_gstart[MAXG + 1];
__device__ float   g_psum[(size_t)MAXG * HH];
__device__ uint2   g_wh[MAXL * 4096];   // W fp16-hi fragments (all layers)
__device__ uint2   g_wl[MAXL * 4096];   // W fp16-residual fragments

// ------------------------------- graph prep ---------------------------------
// count indegree AND record each edge's within-row ordinal (slot 0 = self loop)
__global__ void k_count(const int* __restrict__ dst, int* cnt, int* ord, int e) {
    int i = blockIdx.x * blockDim.x + threadIdx.x;
    if (i < e) ord[i] = atomicAdd(&cnt[dst[i]], 1);
}

__global__ void k_scan1(const int* __restrict__ cnt, int* bsum, float* dis, int n) {
    __shared__ int sh[256];
    int t = threadIdx.x;
    int base = blockIdx.x * 1024 + t * 4;
    int s = 0;
#pragma unroll
    for (int i = 0; i < 4; i++)
        if (base + i < n) {
            int c = cnt[base + i];
            s += c;
            dis[base + i] = rsqrtf((float)c);   // cnt >= 1 always (self loop)
        }
    sh[t] = s;
    __syncthreads();
#pragma unroll
    for (int off = 128; off > 0; off >>= 1) {
        if (t < off) sh[t] += sh[t + off];
        __syncthreads();
    }
    if (t == 0) bsum[blockIdx.x] = sh[0];
}

__global__ void k_scan2(int* bsum, int* rowptr, int nb, int n) {
    __shared__ int sh[256];
    int t = threadIdx.x;
    sh[t] = (t < nb) ? bsum[t] : 0;
    __syncthreads();
    for (int off = 1; off < 256; off <<= 1) {
        int v = (t >= off) ? sh[t - off] : 0;
        __syncthreads();
        sh[t] += v;
        __syncthreads();
    }
    if (t < nb) bsum[t] = (t == 0) ? 0 : sh[t - 1];
    if (t == 0) rowptr[n] = sh[nb - 1];
}

__global__ void k_scan3(const int* __restrict__ cnt, const int* __restrict__ bsumex,
                        int* rowptr, int n) {
    __shared__ int sh[256];
    int t = threadIdx.x;
    int base = blockIdx.x * 1024 + t * 4;
    int v0 = 0, v1 = 0, v2 = 0, v3 = 0;
    if (base + 0 < n) v0 = cnt[base + 0];
    if (base + 1 < n) v1 = cnt[base + 1];
    if (base + 2 < n) v2 = cnt[base + 2];
    if (base + 3 < n) v3 = cnt[base + 3];
    int s = v0 + v1 + v2 + v3;
    sh[t] = s;
    __syncthreads();
    for (int off = 1; off < 256; off <<= 1) {
        int v = (t >= off) ? sh[t - off] : 0;
        __syncthreads();
        sh[t] += v;
        __syncthreads();
    }
    int ex = (t == 0) ? 0 : sh[t - 1];
    int off0 = bsumex[blockIdx.x] + ex;
    if (base + 0 < n) rowptr[base + 0] = off0;
    if (base + 1 < n) rowptr[base + 1] = off0 + v0;
    if (base + 2 < n) rowptr[base + 2] = off0 + v0 + v1;
    if (base + 3 < n) rowptr[base + 3] = off0 + v0 + v1 + v2;
}

// atomic-free fill: pos = rowptr[d] + ordinal (self loop -> slot 0)
__global__ void k_fill(const int* __restrict__ src, const int* __restrict__ dst,
                       const int* __restrict__ ord, const float* __restrict__ dis,
                       const int* __restrict__ rowptr, int2* edges, int e, int n) {
    int i = blockIdx.x * blockDim.x + threadIdx.x;
    if (i >= e + n) return;
    int s, d, pos;
    if (i < e) { s = src[i]; d = dst[i]; pos = rowptr[d] + ord[i]; }
    else       { s = d = i - e;          pos = rowptr[d]; }
    float w = dis[s] * dis[d];
    edges[pos] = make_int2(s, __float_as_int(w));
}

// -------------------------- input fp32 -> fp16 convert -----------------------
__global__ void k_cvt(const float* __restrict__ x, __half* __restrict__ xh, int total4) {
    int i = blockIdx.x * blockDim.x + threadIdx.x;
    if (i >= total4) return;
    float4 v = ((const float4*)x)[i];
    __half2 a = __floats2half2_rn(v.x, v.y);
    __half2 b = __floats2half2_rn(v.z, v.w);
    ((uint2*)xh)[i] = make_uint2(*(uint32_t*)&a, *(uint32_t*)&b);
}

// ----------------------------- SpMM (fp16 gather) ----------------------------
// warp per dst row; lane handles 4 columns (uint2); fp32 accumulate; unroll 8.
__global__ void k_spmm_h(const int* __restrict__ rowptr, const int2* __restrict__ edges,
                         const __half* __restrict__ xin, __half* __restrict__ xout, int n) {
    int row  = (blockIdx.x * blockDim.x + threadIdx.x) >> 5;
    int lane = threadIdx.x & 31;
    if (row >= n) return;
    int s = rowptr[row], e = rowptr[row + 1];
    const uint2* xp = (const uint2*)xin;
    float4 acc = make_float4(0.f, 0.f, 0.f, 0.f);
    int j = s;
    for (; j + 8 <= e; j += 8) {
        int2 e0 = __ldg(&edges[j + 0]);
        int2 e1 = __ldg(&edges[j + 1]);
        int2 e2 = __ldg(&edges[j + 2]);
        int2 e3 = __ldg(&edges[j + 3]);
        int2 e4 = __ldg(&edges[j + 4]);
        int2 e5 = __ldg(&edges[j + 5]);
        int2 e6 = __ldg(&edges[j + 6]);
        int2 e7 = __ldg(&edges[j + 7]);
        uint2 h0 = __ldg(&xp[(size_t)e0.x * 32 + lane]);
        uint2 h1 = __ldg(&xp[(size_t)e1.x * 32 + lane]);
        uint2 h2 = __ldg(&xp[(size_t)e2.x * 32 + lane]);
        uint2 h3 = __ldg(&xp[(size_t)e3.x * 32 + lane]);
        uint2 h4 = __ldg(&xp[(size_t)e4.x * 32 + lane]);
        uint2 h5 = __ldg(&xp[(size_t)e5.x * 32 + lane]);
        uint2 h6 = __ldg(&xp[(size_t)e6.x * 32 + lane]);
        uint2 h7 = __ldg(&xp[(size_t)e7.x * 32 + lane]);
        float2 a, b;
        float w;
        w = __int_as_float(e0.y);
        a = __half22float2(*(const __half2*)&h0.x); b = __half22float2(*(const __half2*)&h0.y);
        acc.x += w * a.x; acc.y += w * a.y; acc.z += w * b.x; acc.w += w * b.y;
        w = __int_as_float(e1.y);
        a = __half22float2(*(const __half2*)&h1.x); b = __half22float2(*(const __half2*)&h1.y);
        acc.x += w * a.x; acc.y += w * a.y; acc.z += w * b.x; acc.w += w * b.y;
        w = __int_as_float(e2.y);
        a = __half22float2(*(const __half2*)&h2.x); b = __half22float2(*(const __half2*)&h2.y);
        acc.x += w * a.x; acc.y += w * a.y; acc.z += w * b.x; acc.w += w * b.y;
        w = __int_as_float(e3.y);
        a = __half22float2(*(const __half2*)&h3.x); b = __half22float2(*(const __half2*)&h3.y);
        acc.x += w * a.x; acc.y += w * a.y; acc.z += w * b.x; acc.w += w * b.y;
        w = __int_as_float(e4.y);
        a = __half22float2(*(const __half2*)&h4.x); b = __half22float2(*(const __half2*)&h4.y);
        acc.x += w * a.x; acc.y += w * a.y; acc.z += w * b.x; acc.w += w * b.y;
        w = __int_as_float(e5.y);
        a = __half22float2(*(const __half2*)&h5.x); b = __half22float2(*(const __half2*)&h5.y);
        acc.x += w * a.x; acc.y += w * a.y; acc.z += w * b.x; acc.w += w * b.y;
        w = __int_as_float(e6.y);
        a = __half22float2(*(const __half2*)&h6.x); b = __half22float2(*(const __half2*)&h6.y);
        acc.x += w * a.x; acc.y += w * a.y; acc.z += w * b.x; acc.w += w * b.y;
        w = __int_as_float(e7.y);
        a = __half22float2(*(const __half2*)&h7.x); b = __half22float2(*(const __half2*)&h7.y);
        acc.x += w * a.x; acc.y += w * a.y; acc.z += w * b.x; acc.w += w * b.y;
    }
    for (; j < e; j++) {
        int2 ed = __ldg(&edges[j]);
        float w = __int_as_float(ed.y);
        uint2 h = __ldg(&xp[(size_t)ed.x * 32 + lane]);
        float2 a = __half22float2(*(const __half2*)&h.x);
        float2 b = __half22float2(*(const __half2*)&h.y);
        acc.x += w * a.x; acc.y += w * a.y; acc.z += w * b.x; acc.w += w * b.y;
    }
    __half2 o0 = __floats2half2_rn(acc.x, acc.y);
    __half2 o1 = __floats2half2_rn(acc.z, acc.w);
    ((uint2*)xout)[(size_t)row * 32 + lane] = make_uint2(*(uint32_t*)&o0, *(uint32_t*)&o1);
}

// ------------------------- tensor-core GEMM helpers --------------------------
__device__ __forceinline__ uint32_t pack_h2(__half lo, __half hi) {
    __half2 h = __halves2half2(lo, hi);
    return *reinterpret_cast<uint32_t*>(&h);
}
__device__ __forceinline__ void mma16816(float* c,
                                         uint32_t a0, uint32_t a1, uint32_t a2, uint32_t a3,
                                         uint32_t b0, uint32_t b1) {
    asm volatile(
        "mma.sync.aligned.m16n8k16.row.col.f32.f16.f16.f32 "
        "{%0,%1,%2,%3}, {%4,%5,%6,%7}, {%8,%9}, {%0,%1,%2,%3};"
        : "+f"(c[0]), "+f"(c[1]), "+f"(c[2]), "+f"(c[3])
        : "r"(a0), "r"(a1), "r"(a2), "r"(a3), "r"(b0), "r"(b1));
}

// ----------------- per-layer W fragment pre-split (ALL layers) ---------------
__global__ void k_prepw16(const float* __restrict__ Ws, uint2* __restrict__ wh,
                          uint2* __restrict__ wl) {
    int l = blockIdx.x >> 4;
    int idx = (blockIdx.x & 15) * 256 + threadIdx.x;   // 0..4095
    const float* W = Ws + (size_t)l * HH * HH;
    int lane = idx & 31, tile = idx >> 5;              // tile 0..127
    int nt = tile & 15, ks = tile >> 4;                // ks 0..7
    int nn = nt * 8 + (lane >> 2);
    int k0 = ks * 16 + (lane & 3) * 2;
    float v00 = W[k0 * HH + nn],       v01 = W[(k0 + 1) * HH + nn];
    float v10 = W[(k0 + 8) * HH + nn], v11 = W[(k0 + 9) * HH + nn];
    __half h00 = __float2half_rn(v00), h01 = __float2half_rn(v01);
    __half h10 = __float2half_rn(v10), h11 = __float2half_rn(v11);
    __half r00 = __float2half_rn(v00 - __half2float(h00));
    __half r01 = __float2half_rn(v01 - __half2float(h01));
    __half r10 = __float2half_rn(v10 - __half2float(h10));
    __half r11 = __float2half_rn(v11 - __half2float(h11));
    wh[l * 4096 + idx] = make_uint2(pack_h2(h00, h01), pack_h2(h10, h11));
    wl[l * 4096 + idx] = make_uint2(pack_h2(r00, r01), pack_h2(r10, r11));
}

// --------------------------------- GEMM --------------------------------------
// out = relu(A @ W + b); A fp16 exact, 2-term W. Block tile 128x128, K=128,
// 8 warps, 35KB smem.
#define SMEM_GEMM16 (128 * 136 * 2)

__global__ __launch_bounds__(256)
void k_gemm_f16(const __half* __restrict__ A,
                const uint2* __restrict__ wh, const uint2* __restrict__ wl,
                const float* __restrict__ bias, __half* __restrict__ out, int n) {
    extern __shared__ __half As[];                // [128][136]
    const int tid  = threadIdx.x;
    const int lane = tid & 31;
    const int warp = tid >> 5;
    const int m0 = blockIdx.x << 7;

    // ---- stage raw A tile (fp16, coalesced uint4 loads, padded smem) ----
#pragma unroll
    for (int i = 0; i < 8; i++) {
        int s   = tid + i * 256;       // 0..2047
        int row = s >> 4, cb = s & 15;
        uint4 v = make_uint4(0u, 0u, 0u, 0u);
        if (m0 + row < n)
            v = ((const uint4*)(A + (size_t)(m0 + row) * HH))[cb];
        *(uint4*)&As[row * 136 + cb * 8] = v;
    }
    __syncthreads();

    const int wm = warp >> 2;      // 0..1  (64 rows each)
    const int wn = warp & 3;       // 0..3  (32 cols each)
    const uint32_t as_base = (uint32_t)__cvta_generic_to_shared(As);

    float acc[4][4][4];
#pragma unroll
    for (int a = 0; a < 4; a++)
#pragma unroll
        for (int b = 0; b < 4; b++)
#pragma unroll
            for (int c = 0; c < 4; c++) acc[a][b][c] = 0.f;

    const int lrow = lane & 15;
    const int lcol = (lane >> 4) * 8;

#pragma unroll
    for (int ks = 0; ks < 8; ks++) {
        uint2 bh[4], bl[4];
#pragma unroll
        for (int nt = 0; nt < 4; nt++) {
            int slot = (ks * 16 + wn * 4 + nt) * 32 + lane;
            bh[nt] = __ldg(&wh[slot]);
            bl[nt] = __ldg(&wl[slot]);
        }
        uint32_t af[4][4];
#pragma unroll
        for (int mt = 0; mt < 4; mt++) {
            int row = wm * 64 + mt * 16 + lrow;
            int col = ks * 16 + lcol;
            uint32_t addr = as_base + (uint32_t)(row * 136 + col) * 2;
            asm volatile(
                "ldmatrix.sync.aligned.m8n8.x4.shared.b16 {%0,%1,%2,%3}, [%4];"
                : "=r"(af[mt][0]), "=r"(af[mt][1]), "=r"(af[mt][2]), "=r"(af[mt][3])
                : "r"(addr));
        }
#pragma unroll
        for (int mt = 0; mt < 4; mt++)
#pragma unroll
            for (int nt = 0; nt < 4; nt++) {
                mma16816(acc[mt][nt], af[mt][0], af[mt][1], af[mt][2], af[mt][3],
                         bh[nt].x, bh[nt].y);
                mma16816(acc[mt][nt], af[mt][0], af[mt][1], af[mt][2], af[mt][3],
                         bl[nt].x, bl[nt].y);
            }
    }

    // ---- epilogue: bias + relu + fp16 store ----
    const int g = lane >> 2, t = lane & 3;
#pragma unroll
    for (int nt = 0; nt < 4; nt++) {
        int c = wn * 32 + nt * 8 + 2 * t;
        float b0 = __ldg(&bias[c]), b1 = __ldg(&bias[c + 1]);
#pragma unroll
        for (int mt = 0; mt < 4; mt++) {
            int m = m0 + wm * 64 + mt * 16 + g;
            if (m < n) {
                __half2 o = __floats2half2_rn(fmaxf(acc[mt][nt][0] + b0, 0.f),
                                              fmaxf(acc[mt][nt][1] + b1, 0.f));
                *(__half2*)&out[(size_t)m * HH + c] = o;
            }
            if (m + 8 < n) {
                __half2 o = __floats2half2_rn(fmaxf(acc[mt][nt][2] + b0, 0.f),
                                              fmaxf(acc[mt][nt][3] + b1, 0.f));
                *(__half2*)&out[(size_t)(m + 8) * HH + c] = o;
            }
        }
    }
}

// ------------------------------ pooling / head ------------------------------
// graph boundaries + zero pooled accumulator + init cnt=1 (self loop)
__global__ void k_gbz(const int* __restrict__ batch, int* gstart, float* psum,
                      int* cnt, int n, int g_num) {
    int i = blockIdx.x * blockDim.x + threadIdx.x;
    if (i < n) cnt[i] = 1;                 // self loop seed for k_count
    if (i < g_num * HH) psum[i] = 0.f;
    if (i <= g_num) {
        int lo = 0, hi = n;
        while (lo < hi) {
            int mid = (lo + hi) >> 1;
            if (batch[mid] < i) lo = mid + 1; else hi = mid;
        }
        gstart[i] = lo;
    }
}

// chunked per-graph partial sums over fp16 activations
__global__ __launch_bounds__(128)
void k_psum(const __half* __restrict__ x, const int* __restrict__ batch,
            float* __restrict__ psum, int n) {
    __shared__ int bsh[256];
    const int t = threadIdx.x;            // column 0..127
    const int r0 = blockIdx.x * 256;
    const int len = min(256, n - r0);
    for (int i = t; i < len; i += 128) bsh[i] = batch[r0 + i];
    __syncthreads();

    if (bsh[0] == bsh[len - 1]) {
        float acc = 0.f;
        int i = 0;
        for (; i + 8 <= len; i += 8) {
            float v0 = __half2float(x[(size_t)(r0 + i + 0) * HH + t]);
            float v1 = __half2float(x[(size_t)(r0 + i + 1) * HH + t]);
            float v2 = __half2float(x[(size_t)(r0 + i + 2) * HH + t]);
            float v3 = __half2float(x[(size_t)(r0 + i + 3) * HH + t]);
            float v4 = __half2float(x[(size_t)(r0 + i + 4) * HH + t]);
            float v5 = __half2float(x[(size_t)(r0 + i + 5) * HH + t]);
            float v6 = __half2float(x[(size_t)(r0 + i + 6) * HH + t]);
            float v7 = __half2float(x[(size_t)(r0 + i + 7) * HH + t]);
            acc += ((v0 + v1) + (v2 + v3)) + ((v4 + v5) + (v6 + v7));
        }
        for (; i < len; i++) acc += __half2float(x[(size_t)(r0 + i) * HH + t]);
        atomicAdd(&psum[(size_t)bsh[0] * HH + t], acc);
    } else {
        float acc = 0.f;
        int curg = bsh[0];
        for (int i = 0; i < len; i++) {
            int g = bsh[i];
            if (g != curg) { atomicAdd(&psum[(size_t)curg * HH + t], acc); acc = 0.f; curg = g; }
            acc += __half2float(x[(size_t)(r0 + i) * HH + t]);
        }
        atomicAdd(&psum[(size_t)curg * HH + t], acc);
    }
}

// head: pooled = psum/cnt ; out = pooled @ W_out + b_out
__global__ void k_out(const float* __restrict__ psum, const int* __restrict__ gstart,
                      const float* __restrict__ Wout, const float* __restrict__ bout,
                      float* __restrict__ out, int C) {
    __shared__ float pr[HH];
    int g = blockIdx.x, t = threadIdx.x;
    float cntf = (float)(gstart[g + 1] - gstart[g]);
    float inv = 1.0f / fmaxf(cntf, 1.0f);
    pr[t] = psum[(size_t)g * HH + t] * inv;
    __syncthreads();
    if (t < C) {
        float s = bout[t];
#pragma unroll 8
        for (int k = 0; k < HH; k++) s += pr[k] * Wout[k * C + t];
        out[g * C + t] = s;
    }
}

// --------------------------------- launch -----------------------------------
extern "C" void kernel_launch(void* const* d_in, const int* in_sizes, int n_in,
                              void* d_out, int out_size) {
    const float* x     = (const float*)d_in[0];
    const int*   ei    = (const int*)d_in[1];
    const int*   batch = (const int*)d_in[2];
    int iw, ibs, iwo, ibo;
    if (n_in >= 8) { iw = 4; ibs = 5; iwo = 6; ibo = 7; }  // num_graphs at index 3
    else           { iw = 3; ibs = 4; iwo = 5; ibo = 6; }
    const float* Ws   = (const float*)d_in[iw];
    const float* bs   = (const float*)d_in[ibs];
    const float* Wout = (const float*)d_in[iwo];
    const float* bout = (const float*)d_in[ibo];

    int N = in_sizes[2];
    int E = in_sizes[1] / 2;
    int H = in_sizes[0] / N;            // expect 128
    int C = in_sizes[ibo];
    int L = in_sizes[ibs] / H;
    int G = out_size / C;
    if (N > MAXN || (E + N) > MAXT || G > MAXG || H != HH || L > MAXL) return;

    void* p;
    cudaGetSymbolAddress(&p, g_cnt);     int*     cnt    = (int*)p;
    cudaGetSymbolAddress(&p, g_dis);     float*   dis    = (float*)p;
    cudaGetSymbolAddress(&p, g_rowptr);  int*     rowptr = (int*)p;
    cudaGetSymbolAddress(&p, g_ord);     int*     ord    = (int*)p;
    cudaGetSymbolAddress(&p, g_edges);   int2*    edges  = (int2*)p;
    cudaGetSymbolAddress(&p, g_xh0);     __half*  xh0    = (__half*)p;
    cudaGetSymbolAddress(&p, g_aggh);    __half*  aggh   = (__half*)p;
    cudaGetSymbolAddress(&p, g_xh1);     __half*  xh1    = (__half*)p;
    cudaGetSymbolAddress(&p, g_xh2);     __half*  xh2    = (__half*)p;
    cudaGetSymbolAddress(&p, g_bsum);    int*     bsum   = (int*)p;
    cudaGetSymbolAddress(&p, g_gstart);  int*     gstart = (int*)p;
    cudaGetSymbolAddress(&p, g_psum);    float*   psum   = (float*)p;
    cudaGetSymbolAddress(&p, g_wh);      uint2*   wh     = (uint2*)p;
    cudaGetSymbolAddress(&p, g_wl);      uint2*   wl     = (uint2*)p;

    cudaFuncSetAttribute(k_gemm_f16, cudaFuncAttributeMaxDynamicSharedMemorySize, SMEM_GEMM16);

    const int* src = ei;
    const int* dst = ei + E;

    // init cnt=1 / graph boundaries / zero pooled accumulator (one pass)
    k_gbz<<<(N + 255) / 256, 256>>>(batch, gstart, psum, cnt, N, G);
    // W fragment pre-split for all layers + input fp16 convert (off critical path)
    k_prepw16<<<16 * L, 256>>>(Ws, wh, wl);
    k_cvt<<<(N * (HH / 4) + 255) / 256, 256>>>(x, xh0, N * (HH / 4));

    k_count<<<(E + 255) / 256, 256>>>(dst, cnt, ord, E);

    int NB = (N + 1023) / 1024;
    k_scan1<<<NB, 256>>>(cnt, bsum, dis, N);
    k_scan2<<<1, 256>>>(bsum, rowptr, NB, N);
    k_scan3<<<NB, 256>>>(cnt, bsum, rowptr, N);
    k_fill <<<(E + N + 255) / 256, 256>>>(src, dst, ord, dis, rowptr, edges, E, N);

    const __half* xin = xh0;
    for (int l = 0; l < L; l++) {
        k_spmm_h<<<(N + 7) / 8, 256>>>(rowptr, edges, xin, aggh, N);
        __half* xout = (l & 1) ? xh2 : xh1;
        k_gemm_f16<<<(N + 127) / 128, 256, SMEM_GEMM16>>>(aggh, wh + (size_t)l * 4096,
                                                          wl + (size_t)l * 4096,
                                                          bs + (size_t)l * H, xout, N);
        xin = xout;
    }

    k_psum<<<(N + 255) / 256, 128>>>(xin, batch, psum, N);
    k_out <<<G, HH>>>(psum, gstart, Wout, bout, (float*)d_out, C);
}